// round 5
// baseline (speedup 1.0000x reference)
#include <cuda_runtime.h>
#include <math.h>

#define NB 2
#define NT 2048
#define NC 1024
#define NH 16
#define ND 64
#define MTOT (NB*NT)   // 4096

// Scratch (device globals)
__device__ float g_q[NB*NH*NT*ND];
__device__ float g_k[NB*NH*NT*ND];
__device__ float g_v[NB*NH*NT*ND];
__device__ float g_y[NB*NT*NC];
__device__ float g_x[MTOT*NC];       // tf32-rounded x
__device__ float g_wq[NC*NC];        // tf32-rounded weights
__device__ float g_wk[NC*NC];
__device__ float g_wv[NC*NC];
__device__ float g_wp[NC*NC];

__device__ __forceinline__ unsigned f2tf(float f) {
    unsigned r;
    asm("cvt.rna.tf32.f32 %0, %1;" : "=r"(r) : "f"(f));
    return r;
}

__device__ __forceinline__ unsigned smem_u32(const void* p) {
    unsigned r;
    asm("{ .reg .u64 t; cvta.to.shared.u64 t, %1; cvt.u32.u64 %0, t; }"
        : "=r"(r) : "l"(p));
    return r;
}

__device__ __forceinline__ void ldsm4(unsigned& r0, unsigned& r1,
                                      unsigned& r2, unsigned& r3, unsigned addr)
{
    asm volatile("ldmatrix.sync.aligned.m8n8.x4.shared.b16 {%0,%1,%2,%3}, [%4];"
                 : "=r"(r0), "=r"(r1), "=r"(r2), "=r"(r3) : "r"(addr));
}

__device__ __forceinline__ void mma_tf32(float c[4], unsigned a0, unsigned a1,
                                         unsigned a2, unsigned a3,
                                         unsigned b0, unsigned b1)
{
    asm volatile(
        "mma.sync.aligned.m16n8k8.row.col.f32.tf32.tf32.f32 "
        "{%0,%1,%2,%3}, {%4,%5,%6,%7}, {%8,%9}, {%0,%1,%2,%3};"
        : "+f"(c[0]), "+f"(c[1]), "+f"(c[2]), "+f"(c[3])
        : "r"(a0), "r"(a1), "r"(a2), "r"(a3), "r"(b0), "r"(b1));
}

__device__ __forceinline__ void cpa16(unsigned dst, const float* src) {
    asm volatile("cp.async.cg.shared.global [%0], [%1], 16;" :: "r"(dst), "l"(src));
}
__device__ __forceinline__ void cp_commit() {
    asm volatile("cp.async.commit_group;");
}
template<int N> __device__ __forceinline__ void cp_wait() {
    asm volatile("cp.async.wait_group %0;" :: "n"(N));
}

// ---------------------------------------------------------------------------
// Prep: round fp32 arrays to tf32 once (which selects destination global)
// ---------------------------------------------------------------------------
__global__ __launch_bounds__(256)
void round_tf32(const float4* __restrict__ s, int which, int n4)
{
    float4* d;
    switch (which) {
        case 0:  d = (float4*)g_x;  break;
        case 1:  d = (float4*)g_wq; break;
        case 2:  d = (float4*)g_wk; break;
        case 3:  d = (float4*)g_wv; break;
        default: d = (float4*)g_wp; break;
    }
    const int i = blockIdx.x * 256 + threadIdx.x;
    if (i < n4) {
        float4 v = s[i];
        uint4 u;
        u.x = f2tf(v.x); u.y = f2tf(v.y); u.z = f2tf(v.z); u.w = f2tf(v.w);
        ((uint4*)d)[i] = u;
    }
}

// ---------------------------------------------------------------------------
// TF32 NT GEMM: out[m,n] = sum_k A[m,k]*W[n,k]. Operands pre-rounded to tf32.
// Block 256 threads (8 warps, 4x2), tile 128x64, BK=32.
// cp.async 2-stage pipeline, 1 syncthreads + 1 wait_group per k-step.
// ---------------------------------------------------------------------------
#define GBM 128
#define GBN 64
#define GBK 32
#define GST 36   // (36r+c)%32 = (4r+c)%32 -> LDSM rows conflict-free; 144B pitch (16B-aligned)
#define STG_WORDS ((GBM+GBN)*GST)        // 6912 words per stage
#define GEMM_SMEM_BYTES (2*STG_WORDS*4)  // 55296

__device__ __forceinline__ void gemm_tc(const float* __restrict__ A,
                                        const float* __restrict__ W,
                                        float C[2][4][4], int m0, int n0)
{
    extern __shared__ unsigned smp[];
    const unsigned sbase = smem_u32(smp);

    const int tid  = threadIdx.x;
    const int wid  = tid >> 5;
    const int lane = tid & 31;
    const int wr   = wid >> 1;   // m offset wr*32
    const int wc   = wid & 1;    // n offset wc*32

    // LDSM lane-derived offsets
    const int aRow = lane & 15;
    const int aCol = (lane >> 4) << 2;
    const int bRow = (((lane >> 4) & 1) << 3) + (lane & 7);
    const int bCol = ((lane >> 3) & 1) << 2;

    // cp.async staging indices
    const int arow = tid >> 1;          // 0..127
    const int acol = (tid & 1) << 4;    // 0 or 16 (4x 16B chunks)
    const int wrow = tid >> 2;          // 0..63
    const int wcol = (tid & 3) << 3;    // 0,8,16,24 (2x 16B chunks)

    const float*  Ap = A + (size_t)(m0 + arow) * NC + acol;
    const float*  Wp = W + (size_t)(n0 + wrow) * NC + wcol;
    const unsigned sA = sbase + (arow * GST + acol) * 4;
    const unsigned sW = sbase + (GBM * GST + wrow * GST + wcol) * 4;

    // prologue: stage 0
    #pragma unroll
    for (int j = 0; j < 4; j++) cpa16(sA + j * 16, Ap + j * 4);
    #pragma unroll
    for (int j = 0; j < 2; j++) cpa16(sW + j * 16, Wp + j * 4);
    cp_commit();

    const int NIT = NC / GBK;   // 32
    for (int it = 0; it < NIT; it++) {
        cp_wait<0>();
        __syncthreads();
        if (it + 1 < NIT) {
            const unsigned so = (unsigned)((it + 1) & 1) * (STG_WORDS * 4);
            const int ko = (it + 1) * GBK;
            #pragma unroll
            for (int j = 0; j < 4; j++) cpa16(sA + so + j * 16, Ap + ko + j * 4);
            #pragma unroll
            for (int j = 0; j < 2; j++) cpa16(sW + so + j * 16, Wp + ko + j * 4);
            cp_commit();
        }
        const unsigned cs    = (unsigned)(it & 1) * (STG_WORDS * 4);
        const unsigned aAddr = sbase + cs + ((wr * 32 + aRow) * GST + aCol) * 4;
        const unsigned bAddr = sbase + cs + (GBM * GST + (wc * 32 + bRow) * GST + bCol) * 4;

        #pragma unroll
        for (int kk = 0; kk < GBK; kk += 8) {
            unsigned a[2][4], b[4][2];
            #pragma unroll
            for (int mt = 0; mt < 2; mt++)
                ldsm4(a[mt][0], a[mt][1], a[mt][2], a[mt][3],
                      aAddr + (mt * 16 * GST + kk) * 4);
            #pragma unroll
            for (int p = 0; p < 2; p++)
                ldsm4(b[2*p][0], b[2*p][1], b[2*p+1][0], b[2*p+1][1],
                      bAddr + (p * 16 * GST + kk) * 4);
            #pragma unroll
            for (int mt = 0; mt < 2; mt++)
                #pragma unroll
                for (int nt = 0; nt < 4; nt++)
                    mma_tf32(C[mt][nt], a[mt][0], a[mt][1], a[mt][2], a[mt][3],
                             b[nt][0], b[nt][1]);
        }
    }
}

// QKV projections (gridDim.z selects Q/K/V); stores tf32-rounded values
__global__ __launch_bounds__(256, 3)
void qkv_kernel(const float* __restrict__ bq, const float* __restrict__ bk,
                const float* __restrict__ bv)
{
    const float* W; const float* bias; float* Out;
    if (blockIdx.z == 0)      { W = g_wq; bias = bq; Out = g_q; }
    else if (blockIdx.z == 1) { W = g_wk; bias = bk; Out = g_k; }
    else                      { W = g_wv; bias = bv; Out = g_v; }

    const int m0 = blockIdx.y * GBM;
    const int n0 = blockIdx.x * GBN;
    float C[2][4][4] = {};
    gemm_tc(g_x, W, C, m0, n0);

    const int lane = threadIdx.x & 31, wid = threadIdx.x >> 5;
    const int g = lane >> 2, t = lane & 3;
    const int wr = wid >> 1, wc = wid & 1;
    const int h = n0 >> 6;

    #pragma unroll
    for (int mt = 0; mt < 2; mt++) {
        #pragma unroll
        for (int rr = 0; rr < 2; rr++) {
            const int m = m0 + wr * 32 + mt * 16 + g + rr * 8;
            const int b = m >> 11;
            const int tt = m & (NT - 1);
            float* op = Out + (((size_t)(b * NH + h)) * NT + tt) * ND;
            #pragma unroll
            for (int nt = 0; nt < 4; nt++) {
                const int nl = wc * 32 + nt * 8 + 2 * t;
                float2 v;
                v.x = __uint_as_float(f2tf(C[mt][nt][rr * 2 + 0] + bias[n0 + nl]));
                v.y = __uint_as_float(f2tf(C[mt][nt][rr * 2 + 1] + bias[n0 + nl + 1]));
                *(float2*)(op + nl) = v;
            }
        }
    }
}

__global__ __launch_bounds__(256, 3)
void proj_kernel(const float* __restrict__ bp, float* __restrict__ out)
{
    const int m0 = blockIdx.y * GBM;
    const int n0 = blockIdx.x * GBN;
    float C[2][4][4] = {};
    gemm_tc(g_y, g_wp, C, m0, n0);

    const int lane = threadIdx.x & 31, wid = threadIdx.x >> 5;
    const int g = lane >> 2, t = lane & 3;
    const int wr = wid >> 1, wc = wid & 1;

    #pragma unroll
    for (int mt = 0; mt < 2; mt++) {
        #pragma unroll
        for (int rr = 0; rr < 2; rr++) {
            const int m = m0 + wr * 32 + mt * 16 + g + rr * 8;
            #pragma unroll
            for (int nt = 0; nt < 4; nt++) {
                const int n = n0 + wc * 32 + nt * 8 + 2 * t;
                float2 v;
                v.x = C[mt][nt][rr * 2 + 0] + bp[n];
                v.y = C[mt][nt][rr * 2 + 1] + bp[n + 1];
                *(float2*)(out + (size_t)m * NC + n) = v;
            }
        }
    }
}

// ---------------------------------------------------------------------------
// Tensor-core flash attention: 256 threads / 8 warps / 128 q-rows per block.
// Operands in gmem are pre-rounded tf32 -> no conversions while staging.
// K staged via cp.async [key][d]; V staged transposed [d][key]; P own buffer.
// ---------------------------------------------------------------------------
#define APD 68
#define ATT_SMEM_WORDS (64*APD + 64*APD + 128*APD)

__global__ __launch_bounds__(256)
void attn_kernel()
{
    extern __shared__ unsigned sm[];
    unsigned* Vt = sm + 64 * APD;      // [64][APD] d-major V tile
    unsigned* Ps = sm + 128 * APD;     // [128][APD] P tile
    const unsigned sbase = smem_u32(sm);
    const unsigned kBase = sbase;                    // Ks
    const unsigned vBase = sbase + 64 * APD * 4;     // Vt
    const unsigned pBase = sbase + 128 * APD * 4;    // Ps

    const int tid  = threadIdx.x;
    const int wid  = tid >> 5;
    const int lane = tid & 31;
    const int g    = lane >> 2;
    const int t    = lane & 3;

    const int bh = blockIdx.y;
    const int qb = gridDim.x - 1 - blockIdx.x;   // heavy blocks first
    const int q0 = qb * 128;
    const int rb = wid * 16;

    const int bRow = (((lane >> 4) & 1) << 3) + (lane & 7);
    const int bCol = ((lane >> 3) & 1) << 2;
    const int aRow = lane & 15;
    const int aCol = (lane >> 4) << 2;

    // ---- Q fragments straight from gmem (pre-rounded; x0.125 exact) ----
    unsigned Qf[8][4];
    {
        const float* qp = g_q + ((size_t)bh * NT + q0 + rb) * ND;
        #pragma unroll
        for (int kt = 0; kt < 8; kt++) {
            Qf[kt][0] = __float_as_uint(qp[(g)     * ND + kt * 8 + t]     * 0.125f);
            Qf[kt][1] = __float_as_uint(qp[(g + 8) * ND + kt * 8 + t]     * 0.125f);
            Qf[kt][2] = __float_as_uint(qp[(g)     * ND + kt * 8 + t + 4] * 0.125f);
            Qf[kt][3] = __float_as_uint(qp[(g + 8) * ND + kt * 8 + t + 4] * 0.125f);
        }
    }

    float Of[8][4];
    #pragma unroll
    for (int nt = 0; nt < 8; nt++)
        #pragma unroll
        for (int j = 0; j < 4; j++) Of[nt][j] = 0.f;
    float mrow[2] = {-1e30f, -1e30f};
    float lrow[2] = {0.f, 0.f};

    // staging indices
    const int kr  = tid >> 2;                 // K row (key)
    const int kc  = (tid & 3) << 4;           // 4x16B chunks
    const int vr  = lane + ((wid & 1) << 5);  // V source row (key)
    const int vcg = (wid >> 1) << 4;          // V 16-col group (d)

    const float* kbase = g_k + (size_t)bh * NT * ND;
    const float* vbase = g_v + (size_t)bh * NT * ND;
    const unsigned kAddr = kBase + (kr * APD + kc) * 4;

    const int ntiles = 2 * qb + 2;

    for (int kt0 = 0; kt0 < ntiles; kt0++) {
        // ---- K via cp.async (overlaps V's LDG latency below) ----
        {
            const float* kp = kbase + ((size_t)(kt0 * 64 + kr)) * ND + kc;
            #pragma unroll
            for (int j = 0; j < 4; j++) cpa16(kAddr + j * 16, kp + j * 4);
            cp_commit();

            const float* vp = vbase + ((size_t)(kt0 * 64 + vr)) * ND + vcg;
            #pragma unroll
            for (int i = 0; i < 4; i++) {
                float4 v = *(const float4*)(vp + i * 4);
                Vt[(vcg + i * 4 + 0) * APD + vr] = __float_as_uint(v.x);
                Vt[(vcg + i * 4 + 1) * APD + vr] = __float_as_uint(v.y);
                Vt[(vcg + i * 4 + 2) * APD + vr] = __float_as_uint(v.z);
                Vt[(vcg + i * 4 + 3) * APD + vr] = __float_as_uint(v.w);
            }
            cp_wait<0>();
        }
        __syncthreads();

        const bool active = (kt0 * 64) <= (q0 + rb + 15);
        if (active) {
            // ---- S = Q K^T ----
            float Sf[8][4];
            #pragma unroll
            for (int nt = 0; nt < 8; nt++)
                #pragma unroll
                for (int j = 0; j < 4; j++) Sf[nt][j] = 0.f;

            #pragma unroll
            for (int kt = 0; kt < 8; kt++) {
                unsigned b[8][2];
                #pragma unroll
                for (int p = 0; p < 4; p++)
                    ldsm4(b[2*p][0], b[2*p][1], b[2*p+1][0], b[2*p+1][1],
                          kBase + ((p * 16 + bRow) * APD + kt * 8 + bCol) * 4);
                #pragma unroll
                for (int nt = 0; nt < 8; nt++)
                    mma_tf32(Sf[nt], Qf[kt][0], Qf[kt][1], Qf[kt][2], Qf[kt][3],
                             b[nt][0], b[nt][1]);
            }

            // ---- causal mask (diagonal tiles only) ----
            if (kt0 >= 2 * qb) {
                #pragma unroll
                for (int nt = 0; nt < 8; nt++)
                    #pragma unroll
                    for (int j = 0; j < 4; j++) {
                        const int key = kt0 * 64 + nt * 8 + 2 * t + (j & 1);
                        const int qr  = q0 + rb + g + (j >> 1) * 8;
                        if (key > qr) Sf[nt][j] = -1e30f;
                    }
            }

            // ---- online softmax ----
            #pragma unroll
            for (int r = 0; r < 2; r++) {
                float rm = -1e30f;
                #pragma unroll
                for (int nt = 0; nt < 8; nt++) {
                    rm = fmaxf(rm, Sf[nt][2 * r]);
                    rm = fmaxf(rm, Sf[nt][2 * r + 1]);
                }
                rm = fmaxf(rm, __shfl_xor_sync(0xffffffff, rm, 1));
                rm = fmaxf(rm, __shfl_xor_sync(0xffffffff, rm, 2));
                const float mn   = fmaxf(mrow[r], rm);
                const float corr = __expf(mrow[r] - mn);
                mrow[r] = mn;
                float rs = 0.f;
                #pragma unroll
                for (int nt = 0; nt < 8; nt++) {
                    const float p0 = __expf(Sf[nt][2 * r]     - mn);
                    const float p1 = __expf(Sf[nt][2 * r + 1] - mn);
                    Sf[nt][2 * r] = p0; Sf[nt][2 * r + 1] = p1;
                    rs += p0 + p1;
                }
                rs += __shfl_xor_sync(0xffffffff, rs, 1);
                rs += __shfl_xor_sync(0xffffffff, rs, 2);
                lrow[r] = lrow[r] * corr + rs;
                #pragma unroll
                for (int nt = 0; nt < 8; nt++) {
                    Of[nt][2 * r]     *= corr;
                    Of[nt][2 * r + 1] *= corr;
                }
            }

            // ---- write P into this warp's slice ----
            #pragma unroll
            for (int nt = 0; nt < 8; nt++) {
                uint2 u0; u0.x = f2tf(Sf[nt][0]); u0.y = f2tf(Sf[nt][1]);
                *(uint2*)&Ps[(rb + g)     * APD + nt * 8 + 2 * t] = u0;
                uint2 u1; u1.x = f2tf(Sf[nt][2]); u1.y = f2tf(Sf[nt][3]);
                *(uint2*)&Ps[(rb + g + 8) * APD + nt * 8 + 2 * t] = u1;
            }
            __syncwarp();

            // ---- O += P V ----
            #pragma unroll
            for (int kt = 0; kt < 8; kt++) {
                unsigned a0, a1, a2, a3;
                ldsm4(a0, a1, a2, a3,
                      pBase + ((rb + aRow) * APD + kt * 8 + aCol) * 4);
                unsigned b[8][2];
                #pragma unroll
                for (int p = 0; p < 4; p++)
                    ldsm4(b[2*p][0], b[2*p][1], b[2*p+1][0], b[2*p+1][1],
                          vBase + ((p * 16 + bRow) * APD + kt * 8 + bCol) * 4);
                #pragma unroll
                for (int nt = 0; nt < 8; nt++)
                    mma_tf32(Of[nt], a0, a1, a2, a3, b[nt][0], b[nt][1]);
            }
        }
        __syncthreads();
    }

    // ---- epilogue: divide by l, store tf32-rounded for proj ----
    const float inv0 = 1.0f / lrow[0];
    const float inv1 = 1.0f / lrow[1];
    const int b = bh >> 4;
    const int h = bh & 15;
    float* yp = g_y + ((size_t)(b * NT) + q0 + rb) * NC + h * ND;

    #pragma unroll
    for (int nt = 0; nt < 8; nt++) {
        const int c = nt * 8 + 2 * t;
        float2 v0;
        v0.x = __uint_as_float(f2tf(Of[nt][0] * inv0));
        v0.y = __uint_as_float(f2tf(Of[nt][1] * inv0));
        *(float2*)(yp + (size_t)g * NC + c) = v0;
        float2 v1;
        v1.x = __uint_as_float(f2tf(Of[nt][2] * inv1));
        v1.y = __uint_as_float(f2tf(Of[nt][3] * inv1));
        *(float2*)(yp + (size_t)(g + 8) * NC + c) = v1;
    }
}

// ---------------------------------------------------------------------------
extern "C" void kernel_launch(void* const* d_in, const int* in_sizes, int n_in,
                              void* d_out, int out_size)
{
    const float* x  = (const float*)d_in[0];
    const float* Wk = (const float*)d_in[1];
    const float* bk = (const float*)d_in[2];
    const float* Wq = (const float*)d_in[3];
    const float* bq = (const float*)d_in[4];
    const float* Wv = (const float*)d_in[5];
    const float* bv = (const float*)d_in[6];
    const float* Wp = (const float*)d_in[7];
    const float* bp = (const float*)d_in[8];
    float* out = (float*)d_out;

    static bool attr_done = false;
    if (!attr_done) {
        cudaFuncSetAttribute(qkv_kernel,
                             cudaFuncAttributeMaxDynamicSharedMemorySize, GEMM_SMEM_BYTES);
        cudaFuncSetAttribute(proj_kernel,
                             cudaFuncAttributeMaxDynamicSharedMemorySize, GEMM_SMEM_BYTES);
        cudaFuncSetAttribute(attn_kernel,
                             cudaFuncAttributeMaxDynamicSharedMemorySize, ATT_SMEM_WORDS * 4);
        attr_done = true;
    }

    // prep: tf32-round x and the 4 weight matrices
    round_tf32<<<(MTOT*NC/4 + 255)/256, 256>>>((const float4*)x,  0, MTOT*NC/4);
    round_tf32<<<(NC*NC/4   + 255)/256, 256>>>((const float4*)Wq, 1, NC*NC/4);
    round_tf32<<<(NC*NC/4   + 255)/256, 256>>>((const float4*)Wk, 2, NC*NC/4);
    round_tf32<<<(NC*NC/4   + 255)/256, 256>>>((const float4*)Wv, 3, NC*NC/4);
    round_tf32<<<(NC*NC/4   + 255)/256, 256>>>((const float4*)Wp, 4, NC*NC/4);

    dim3 gq(NC / GBN, MTOT / GBM, 3);
    qkv_kernel<<<gq, 256, GEMM_SMEM_BYTES>>>(bq, bk, bv);

    dim3 ga(NT / 128, NB * NH);
    attn_kernel<<<ga, 256, ATT_SMEM_WORDS * 4>>>();

    dim3 gp(NC / GBN, MTOT / GBM);
    proj_kernel<<<gp, 256, GEMM_SMEM_BYTES>>>(bp, out);
}

// round 7
// speedup vs baseline: 1.0031x; 1.0031x over previous
#include <cuda_runtime.h>
#include <math.h>
#include <stdint.h>

#define NB 2
#define NT 2048
#define NC 1024
#define NH 16
#define ND 64
#define MTOT (NB*NT)   // 4096

// Scratch (device globals)
__device__ float g_q[NB*NH*NT*ND];
__device__ float g_k[NB*NH*NT*ND];
__device__ float g_v[NB*NH*NT*ND];
__device__ float g_y[NB*NT*NC];
__device__ float g_x[MTOT*NC];       // tf32-rounded x
__device__ float g_wq[NC*NC];        // tf32-rounded weights
__device__ float g_wk[NC*NC];
__device__ float g_wv[NC*NC];
__device__ float g_wp[NC*NC];

__device__ __forceinline__ unsigned f2tf(float f) {
    unsigned r;
    asm("cvt.rna.tf32.f32 %0, %1;" : "=r"(r) : "f"(f));
    return r;
}

__device__ __forceinline__ unsigned smem_u32(const void* p) {
    unsigned r;
    asm("{ .reg .u64 t; cvta.to.shared.u64 t, %1; cvt.u32.u64 %0, t; }"
        : "=r"(r) : "l"(p));
    return r;
}

__device__ __forceinline__ void ldsm4(unsigned& r0, unsigned& r1,
                                      unsigned& r2, unsigned& r3, unsigned addr)
{
    asm volatile("ldmatrix.sync.aligned.m8n8.x4.shared.b16 {%0,%1,%2,%3}, [%4];"
                 : "=r"(r0), "=r"(r1), "=r"(r2), "=r"(r3) : "r"(addr));
}

__device__ __forceinline__ void mma_tf32(float c[4], unsigned a0, unsigned a1,
                                         unsigned a2, unsigned a3,
                                         unsigned b0, unsigned b1)
{
    asm volatile(
        "mma.sync.aligned.m16n8k8.row.col.f32.tf32.tf32.f32 "
        "{%0,%1,%2,%3}, {%4,%5,%6,%7}, {%8,%9}, {%0,%1,%2,%3};"
        : "+f"(c[0]), "+f"(c[1]), "+f"(c[2]), "+f"(c[3])
        : "r"(a0), "r"(a1), "r"(a2), "r"(a3), "r"(b0), "r"(b1));
}

__device__ __forceinline__ void cpa16(unsigned dst, const float* src) {
    asm volatile("cp.async.cg.shared.global [%0], [%1], 16;" :: "r"(dst), "l"(src));
}
__device__ __forceinline__ void cp_commit() {
    asm volatile("cp.async.commit_group;");
}
template<int N> __device__ __forceinline__ void cp_wait() {
    asm volatile("cp.async.wait_group %0;" :: "n"(N));
}

// ---------------------------------------------------------------------------
// Prep (single launch): round x and the 4 weight matrices to tf32.
// Layout: [0, 1M) float4 -> g_x; then 4x 256K float4 -> wq, wk, wv, wp.
// ---------------------------------------------------------------------------
#define X4   (MTOT*NC/4)   // 1048576
#define W4   (NC*NC/4)     // 262144
#define TOT4 (X4 + 4*W4)   // 2097152

__global__ __launch_bounds__(256)
void prep_tf32(const float4* __restrict__ x,  const float4* __restrict__ wq,
               const float4* __restrict__ wk, const float4* __restrict__ wv,
               const float4* __restrict__ wp)
{
    const int i = blockIdx.x * 256 + threadIdx.x;
    if (i >= TOT4) return;
    const float4* s; float4* d; int off;
    if (i < X4) { s = x; d = (float4*)g_x; off = i; }
    else {
        const int j = i - X4;
        const int w = j >> 18;           // /262144
        off = j & (W4 - 1);
        switch (w) {
            case 0:  s = wq; d = (float4*)g_wq; break;
            case 1:  s = wk; d = (float4*)g_wk; break;
            case 2:  s = wv; d = (float4*)g_wv; break;
            default: s = wp; d = (float4*)g_wp; break;
        }
    }
    float4 v = s[off];
    uint4 u;
    u.x = f2tf(v.x); u.y = f2tf(v.y); u.z = f2tf(v.z); u.w = f2tf(v.w);
    ((uint4*)d)[off] = u;
}

// ---------------------------------------------------------------------------
// TF32 NT GEMM (mma.sync): out[m,n] = sum_k A[m,k]*W[n,k]. Inputs pre-rounded.
// Block 256 threads (8 warps, 4x2), tile 128x64, BK=32, cp.async 2-stage.
// ---------------------------------------------------------------------------
#define GBM 128
#define GBN 64
#define GBK 32
#define GST 36
#define STG_WORDS ((GBM+GBN)*GST)
#define GEMM_SMEM_BYTES (2*STG_WORDS*4)

__device__ __forceinline__ void gemm_tc(const float* __restrict__ A,
                                        const float* __restrict__ W,
                                        float C[2][4][4], int m0, int n0)
{
    extern __shared__ unsigned smp[];
    const unsigned sbase = smem_u32(smp);

    const int tid  = threadIdx.x;
    const int wid  = tid >> 5;
    const int lane = tid & 31;
    const int wr   = wid >> 1;
    const int wc   = wid & 1;

    const int aRow = lane & 15;
    const int aCol = (lane >> 4) << 2;
    const int bRow = (((lane >> 4) & 1) << 3) + (lane & 7);
    const int bCol = ((lane >> 3) & 1) << 2;

    const int arow = tid >> 1;
    const int acol = (tid & 1) << 4;
    const int wrow = tid >> 2;
    const int wcol = (tid & 3) << 3;

    const float*  Ap = A + (size_t)(m0 + arow) * NC + acol;
    const float*  Wp = W + (size_t)(n0 + wrow) * NC + wcol;
    const unsigned sA = sbase + (arow * GST + acol) * 4;
    const unsigned sW = sbase + (GBM * GST + wrow * GST + wcol) * 4;

    #pragma unroll
    for (int j = 0; j < 4; j++) cpa16(sA + j * 16, Ap + j * 4);
    #pragma unroll
    for (int j = 0; j < 2; j++) cpa16(sW + j * 16, Wp + j * 4);
    cp_commit();

    const int NIT = NC / GBK;
    for (int it = 0; it < NIT; it++) {
        cp_wait<0>();
        __syncthreads();
        if (it + 1 < NIT) {
            const unsigned so = (unsigned)((it + 1) & 1) * (STG_WORDS * 4);
            const int ko = (it + 1) * GBK;
            #pragma unroll
            for (int j = 0; j < 4; j++) cpa16(sA + so + j * 16, Ap + ko + j * 4);
            #pragma unroll
            for (int j = 0; j < 2; j++) cpa16(sW + so + j * 16, Wp + ko + j * 4);
            cp_commit();
        }
        const unsigned cs    = (unsigned)(it & 1) * (STG_WORDS * 4);
        const unsigned aAddr = sbase + cs + ((wr * 32 + aRow) * GST + aCol) * 4;
        const unsigned bAddr = sbase + cs + (GBM * GST + (wc * 32 + bRow) * GST + bCol) * 4;

        #pragma unroll
        for (int kk = 0; kk < GBK; kk += 8) {
            unsigned a[2][4], b[4][2];
            #pragma unroll
            for (int mt = 0; mt < 2; mt++)
                ldsm4(a[mt][0], a[mt][1], a[mt][2], a[mt][3],
                      aAddr + (mt * 16 * GST + kk) * 4);
            #pragma unroll
            for (int p = 0; p < 2; p++)
                ldsm4(b[2*p][0], b[2*p][1], b[2*p+1][0], b[2*p+1][1],
                      bAddr + (p * 16 * GST + kk) * 4);
            #pragma unroll
            for (int mt = 0; mt < 2; mt++)
                #pragma unroll
                for (int nt = 0; nt < 4; nt++)
                    mma_tf32(C[mt][nt], a[mt][0], a[mt][1], a[mt][2], a[mt][3],
                             b[nt][0], b[nt][1]);
        }
    }
}

__global__ __launch_bounds__(256, 3)
void qkv_kernel(const float* __restrict__ bq, const float* __restrict__ bk,
                const float* __restrict__ bv)
{
    const float* W; const float* bias; float* Out;
    if (blockIdx.z == 0)      { W = g_wq; bias = bq; Out = g_q; }
    else if (blockIdx.z == 1) { W = g_wk; bias = bk; Out = g_k; }
    else                      { W = g_wv; bias = bv; Out = g_v; }

    const int m0 = blockIdx.y * GBM;
    const int n0 = blockIdx.x * GBN;
    float C[2][4][4] = {};
    gemm_tc(g_x, W, C, m0, n0);

    const int lane = threadIdx.x & 31, wid = threadIdx.x >> 5;
    const int g = lane >> 2, t = lane & 3;
    const int wr = wid >> 1, wc = wid & 1;
    const int h = n0 >> 6;

    #pragma unroll
    for (int mt = 0; mt < 2; mt++) {
        #pragma unroll
        for (int rr = 0; rr < 2; rr++) {
            const int m = m0 + wr * 32 + mt * 16 + g + rr * 8;
            const int b = m >> 11;
            const int tt = m & (NT - 1);
            float* op = Out + (((size_t)(b * NH + h)) * NT + tt) * ND;
            #pragma unroll
            for (int nt = 0; nt < 4; nt++) {
                const int nl = wc * 32 + nt * 8 + 2 * t;
                float2 v;
                v.x = __uint_as_float(f2tf(C[mt][nt][rr * 2 + 0] + bias[n0 + nl]));
                v.y = __uint_as_float(f2tf(C[mt][nt][rr * 2 + 1] + bias[n0 + nl + 1]));
                *(float2*)(op + nl) = v;
            }
        }
    }
}

__global__ __launch_bounds__(256, 3)
void proj_kernel(const float* __restrict__ bp, float* __restrict__ out)
{
    const int m0 = blockIdx.y * GBM;
    const int n0 = blockIdx.x * GBN;
    float C[2][4][4] = {};
    gemm_tc(g_y, g_wp, C, m0, n0);

    const int lane = threadIdx.x & 31, wid = threadIdx.x >> 5;
    const int g = lane >> 2, t = lane & 3;
    const int wr = wid >> 1, wc = wid & 1;

    #pragma unroll
    for (int mt = 0; mt < 2; mt++) {
        #pragma unroll
        for (int rr = 0; rr < 2; rr++) {
            const int m = m0 + wr * 32 + mt * 16 + g + rr * 8;
            #pragma unroll
            for (int nt = 0; nt < 4; nt++) {
                const int n = n0 + wc * 32 + nt * 8 + 2 * t;
                float2 v;
                v.x = C[mt][nt][rr * 2 + 0] + bp[n];
                v.y = C[mt][nt][rr * 2 + 1] + bp[n + 1];
                *(float2*)(out + (size_t)m * NC + n) = v;
            }
        }
    }
}

// ---------------------------------------------------------------------------
// Tensor-core flash attention, DOUBLE-BUFFERED staging.
// 256 threads / 8 warps / 128 q-rows per block.
// K tiles: cp.async into 2 buffers, committed one tile ahead.
// V tiles: prefetched to registers during compute, transposed into the
// alternate buffer afterwards. One __syncthreads per tile.
// ---------------------------------------------------------------------------
#define APD 68
#define KVW (64*APD)                         // words per K or V buffer
#define ATT_SMEM_WORDS (4*KVW + 128*APD)     // K0 K1 V0 V1 P

__global__ __launch_bounds__(256)
void attn_kernel()
{
    extern __shared__ unsigned sm[];
    const unsigned sbase = smem_u32(sm);
    const unsigned pBase = sbase + 4 * KVW * 4;
    unsigned* Ps = sm + 4 * KVW;

    const int tid  = threadIdx.x;
    const int wid  = tid >> 5;
    const int lane = tid & 31;
    const int g    = lane >> 2;
    const int t    = lane & 3;

    const int bh = blockIdx.y;
    const int qb = gridDim.x - 1 - blockIdx.x;   // heavy blocks first
    const int q0 = qb * 128;
    const int rb = wid * 16;

    const int bRow = (((lane >> 4) & 1) << 3) + (lane & 7);
    const int bCol = ((lane >> 3) & 1) << 2;
    const int aRow = lane & 15;
    const int aCol = (lane >> 4) << 2;

    // ---- Q fragments straight from gmem (pre-rounded; x0.125 exact) ----
    unsigned Qf[8][4];
    {
        const float* qp = g_q + ((size_t)bh * NT + q0 + rb) * ND;
        #pragma unroll
        for (int kt = 0; kt < 8; kt++) {
            Qf[kt][0] = __float_as_uint(qp[(g)     * ND + kt * 8 + t]     * 0.125f);
            Qf[kt][1] = __float_as_uint(qp[(g + 8) * ND + kt * 8 + t]     * 0.125f);
            Qf[kt][2] = __float_as_uint(qp[(g)     * ND + kt * 8 + t + 4] * 0.125f);
            Qf[kt][3] = __float_as_uint(qp[(g + 8) * ND + kt * 8 + t + 4] * 0.125f);
        }
    }

    float Of[8][4];
    #pragma unroll
    for (int nt = 0; nt < 8; nt++)
        #pragma unroll
        for (int j = 0; j < 4; j++) Of[nt][j] = 0.f;
    float mrow[2] = {-1e30f, -1e30f};
    float lrow[2] = {0.f, 0.f};

    // staging indices
    const int kr  = tid >> 2;                 // K row (key)
    const int kc  = (tid & 3) << 4;           // 4x16B chunks
    const int vr  = lane + ((wid & 1) << 5);  // V source row (key)
    const int vcg = (wid >> 1) << 4;          // V 16-col group (d)

    const float* kbase = g_k + (size_t)bh * NT * ND;
    const float* vbase = g_v + (size_t)bh * NT * ND;
    const unsigned kOff = (kr * APD + kc) * 4;   // within a K buffer

    const int ntiles = 2 * qb + 2;

    // ---- prologue: stage tile 0 ----
    {
        const float* kp = kbase + (size_t)kr * ND + kc;
        #pragma unroll
        for (int j = 0; j < 4; j++) cpa16(sbase + kOff + j * 16, kp + j * 4);
        cp_commit();

        const float* vp = vbase + (size_t)vr * ND + vcg;
        unsigned* Vt0 = sm + 2 * KVW;
        #pragma unroll
        for (int i = 0; i < 4; i++) {
            float4 v = *(const float4*)(vp + i * 4);
            Vt0[(vcg + i * 4 + 0) * APD + vr] = __float_as_uint(v.x);
            Vt0[(vcg + i * 4 + 1) * APD + vr] = __float_as_uint(v.y);
            Vt0[(vcg + i * 4 + 2) * APD + vr] = __float_as_uint(v.z);
            Vt0[(vcg + i * 4 + 3) * APD + vr] = __float_as_uint(v.w);
        }
        cp_wait<0>();
    }
    __syncthreads();

    for (int kt0 = 0; kt0 < ntiles; kt0++) {
        const int cur = kt0 & 1;
        const int nxt = cur ^ 1;
        const bool havenext = (kt0 + 1 < ntiles);

        // ---- issue next tile's loads before computing this one ----
        float4 vpre[4];
        if (havenext) {
            const float* kp = kbase + ((size_t)((kt0 + 1) * 64 + kr)) * ND + kc;
            const unsigned kDst = sbase + (unsigned)nxt * KVW * 4 + kOff;
            #pragma unroll
            for (int j = 0; j < 4; j++) cpa16(kDst + j * 16, kp + j * 4);
            cp_commit();
            const float* vp = vbase + ((size_t)((kt0 + 1) * 64 + vr)) * ND + vcg;
            #pragma unroll
            for (int i = 0; i < 4; i++) vpre[i] = *(const float4*)(vp + i * 4);
        }

        const unsigned kBuf = sbase + (unsigned)cur * KVW * 4;
        const unsigned vBuf = sbase + (unsigned)(2 + cur) * KVW * 4;

        const bool active = (kt0 * 64) <= (q0 + rb + 15);
        if (active) {
            // ---- S = Q K^T ----
            float Sf[8][4];
            #pragma unroll
            for (int nt = 0; nt < 8; nt++)
                #pragma unroll
                for (int j = 0; j < 4; j++) Sf[nt][j] = 0.f;

            #pragma unroll
            for (int kt = 0; kt < 8; kt++) {
                unsigned b[8][2];
                #pragma unroll
                for (int p = 0; p < 4; p++)
                    ldsm4(b[2*p][0], b[2*p][1], b[2*p+1][0], b[2*p+1][1],
                          kBuf + ((p * 16 + bRow) * APD + kt * 8 + bCol) * 4);
                #pragma unroll
                for (int nt = 0; nt < 8; nt++)
                    mma_tf32(Sf[nt], Qf[kt][0], Qf[kt][1], Qf[kt][2], Qf[kt][3],
                             b[nt][0], b[nt][1]);
            }

            // ---- causal mask (diagonal tiles only) ----
            if (kt0 >= 2 * qb) {
                #pragma unroll
                for (int nt = 0; nt < 8; nt++)
                    #pragma unroll
                    for (int j = 0; j < 4; j++) {
                        const int key = kt0 * 64 + nt * 8 + 2 * t + (j & 1);
                        const int qr  = q0 + rb + g + (j >> 1) * 8;
                        if (key > qr) Sf[nt][j] = -1e30f;
                    }
            }

            // ---- online softmax ----
            #pragma unroll
            for (int r = 0; r < 2; r++) {
                float rm = -1e30f;
                #pragma unroll
                for (int nt = 0; nt < 8; nt++) {
                    rm = fmaxf(rm, Sf[nt][2 * r]);
                    rm = fmaxf(rm, Sf[nt][2 * r + 1]);
                }
                rm = fmaxf(rm, __shfl_xor_sync(0xffffffff, rm, 1));
                rm = fmaxf(rm, __shfl_xor_sync(0xffffffff, rm, 2));
                const float mn   = fmaxf(mrow[r], rm);
                const float corr = __expf(mrow[r] - mn);
                mrow[r] = mn;
                float rs = 0.f;
                #pragma unroll
                for (int nt = 0; nt < 8; nt++) {
                    const float p0 = __expf(Sf[nt][2 * r]     - mn);
                    const float p1 = __expf(Sf[nt][2 * r + 1] - mn);
                    Sf[nt][2 * r] = p0; Sf[nt][2 * r + 1] = p1;
                    rs += p0 + p1;
                }
                rs += __shfl_xor_sync(0xffffffff, rs, 1);
                rs += __shfl_xor_sync(0xffffffff, rs, 2);
                lrow[r] = lrow[r] * corr + rs;
                #pragma unroll
                for (int nt = 0; nt < 8; nt++) {
                    Of[nt][2 * r]     *= corr;
                    Of[nt][2 * r + 1] *= corr;
                }
            }

            // ---- write P into this warp's slice ----
            #pragma unroll
            for (int nt = 0; nt < 8; nt++) {
                uint2 u0; u0.x = f2tf(Sf[nt][0]); u0.y = f2tf(Sf[nt][1]);
                *(uint2*)&Ps[(rb + g)     * APD + nt * 8 + 2 * t] = u0;
                uint2 u1; u1.x = f2tf(Sf[nt][2]); u1.y = f2tf(Sf[nt][3]);
                *(uint2*)&Ps[(rb + g + 8) * APD + nt * 8 + 2 * t] = u1;
            }
            __syncwarp();

            // ---- O += P V ----
            #pragma unroll
            for (int kt = 0; kt < 8; kt++) {
                unsigned a0, a1, a2, a3;
                ldsm4(a0, a1, a2, a3,
                      pBase + ((rb + aRow) * APD + kt * 8 + aCol) * 4);
                unsigned b[8][2];
                #pragma unroll
                for (int p = 0; p < 4; p++)
                    ldsm4(b[2*p][0], b[2*p][1], b[2*p+1][0], b[2*p+1][1],
                          vBuf + ((p * 16 + bRow) * APD + kt * 8 + bCol) * 4);
                #pragma unroll
                for (int nt = 0; nt < 8; nt++)
                    mma_tf32(Of[nt], a0, a1, a2, a3, b[nt][0], b[nt][1]);
            }
        }

        // ---- finish next tile's staging ----
        if (havenext) {
            unsigned* VtN = sm + (2 + nxt) * KVW;
            #pragma unroll
            for (int i = 0; i < 4; i++) {
                VtN[(vcg + i * 4 + 0) * APD + vr] = __float_as_uint(vpre[i].x);
                VtN[(vcg + i * 4 + 1) * APD + vr] = __float_as_uint(vpre[i].y);
                VtN[(vcg + i * 4 + 2) * APD + vr] = __float_as_uint(vpre[i].z);
                VtN[(vcg + i * 4 + 3) * APD + vr] = __float_as_uint(vpre[i].w);
            }
            cp_wait<0>();
        }
        __syncthreads();
    }

    // ---- epilogue: divide by l, store tf32-rounded for proj ----
    const float inv0 = 1.0f / lrow[0];
    const float inv1 = 1.0f / lrow[1];
    const int b = bh >> 4;
    const int h = bh & 15;
    float* yp = g_y + ((size_t)(b * NT) + q0 + rb) * NC + h * ND;

    #pragma unroll
    for (int nt = 0; nt < 8; nt++) {
        const int c = nt * 8 + 2 * t;
        float2 v0;
        v0.x = __uint_as_float(f2tf(Of[nt][0] * inv0));
        v0.y = __uint_as_float(f2tf(Of[nt][1] * inv0));
        *(float2*)(yp + (size_t)g * NC + c) = v0;
        float2 v1;
        v1.x = __uint_as_float(f2tf(Of[nt][2] * inv1));
        v1.y = __uint_as_float(f2tf(Of[nt][3] * inv1));
        *(float2*)(yp + (size_t)(g + 8) * NC + c) = v1;
    }
}

// ---------------------------------------------------------------------------
extern "C" void kernel_launch(void* const* d_in, const int* in_sizes, int n_in,
                              void* d_out, int out_size)
{
    const float* x  = (const float*)d_in[0];
    const float* Wk = (const float*)d_in[1];
    const float* bk = (const float*)d_in[2];
    const float* Wq = (const float*)d_in[3];
    const float* bq = (const float*)d_in[4];
    const float* Wv = (const float*)d_in[5];
    const float* bv = (const float*)d_in[6];
    const float* Wp = (const float*)d_in[7];
    const float* bp = (const float*)d_in[8];
    float* out = (float*)d_out;

    static bool attr_done = false;
    if (!attr_done) {
        cudaFuncSetAttribute(qkv_kernel,
                             cudaFuncAttributeMaxDynamicSharedMemorySize, GEMM_SMEM_BYTES);
        cudaFuncSetAttribute(proj_kernel,
                             cudaFuncAttributeMaxDynamicSharedMemorySize, GEMM_SMEM_BYTES);
        cudaFuncSetAttribute(attn_kernel,
                             cudaFuncAttributeMaxDynamicSharedMemorySize, ATT_SMEM_WORDS * 4);
        attr_done = true;
    }

    prep_tf32<<<(TOT4 + 255) / 256, 256>>>((const float4*)x,  (const float4*)Wq,
                                           (const float4*)Wk, (const float4*)Wv,
                                           (const float4*)Wp);

    dim3 gq(NC / GBN, MTOT / GBM, 3);
    qkv_kernel<<<gq, 256, GEMM_SMEM_BYTES>>>(bq, bk, bv);

    dim3 ga(NT / 128, NB * NH);
    attn_kernel<<<ga, 256, ATT_SMEM_WORDS * 4>>>();

    dim3 gp(NC / GBN, MTOT / GBM);
    proj_kernel<<<gp, 256, GEMM_SMEM_BYTES>>>(bp, out);
}

// round 9
// speedup vs baseline: 2.3928x; 2.3853x over previous
#include <cuda_runtime.h>
#include <cuda_fp16.h>
#include <math.h>
#include <stdint.h>

#define NB 2
#define NT 2048
#define NC 1024
#define NH 16
#define ND 64
#define MTOT (NB*NT)   // 4096

// Scratch (device globals) — all fp16 now
__device__ __half g_q[NB*NH*NT*ND];
__device__ __half g_k[NB*NH*NT*ND];
__device__ __half g_v[NB*NH*NT*ND];
__device__ __half g_y[NB*NT*NC];
__device__ __half g_x[MTOT*NC];
__device__ __half g_wq[NC*NC];
__device__ __half g_wk[NC*NC];
__device__ __half g_wv[NC*NC];
__device__ __half g_wp[NC*NC];

__device__ __forceinline__ unsigned smem_u32(const void* p) {
    unsigned r;
    asm("{ .reg .u64 t; cvta.to.shared.u64 t, %1; cvt.u32.u64 %0, t; }"
        : "=r"(r) : "l"(p));
    return r;
}

__device__ __forceinline__ void ldsm4(unsigned& r0, unsigned& r1,
                                      unsigned& r2, unsigned& r3, unsigned addr)
{
    asm volatile("ldmatrix.sync.aligned.m8n8.x4.shared.b16 {%0,%1,%2,%3}, [%4];"
                 : "=r"(r0), "=r"(r1), "=r"(r2), "=r"(r3) : "r"(addr));
}
__device__ __forceinline__ void ldsm4t(unsigned& r0, unsigned& r1,
                                       unsigned& r2, unsigned& r3, unsigned addr)
{
    asm volatile("ldmatrix.sync.aligned.m8n8.x4.trans.shared.b16 {%0,%1,%2,%3}, [%4];"
                 : "=r"(r0), "=r"(r1), "=r"(r2), "=r"(r3) : "r"(addr));
}

// fp16 MMA, fp32 accumulate: D(16x8) += A(16x16) * B(16x8)
__device__ __forceinline__ void mma_f16(float c[4], unsigned a0, unsigned a1,
                                        unsigned a2, unsigned a3,
                                        unsigned b0, unsigned b1)
{
    asm volatile(
        "mma.sync.aligned.m16n8k16.row.col.f32.f16.f16.f32 "
        "{%0,%1,%2,%3}, {%4,%5,%6,%7}, {%8,%9}, {%0,%1,%2,%3};"
        : "+f"(c[0]), "+f"(c[1]), "+f"(c[2]), "+f"(c[3])
        : "r"(a0), "r"(a1), "r"(a2), "r"(a3), "r"(b0), "r"(b1));
}

__device__ __forceinline__ void cpa16(unsigned dst, const void* src) {
    asm volatile("cp.async.cg.shared.global [%0], [%1], 16;" :: "r"(dst), "l"(src));
}
__device__ __forceinline__ void cp_commit() {
    asm volatile("cp.async.commit_group;");
}
template<int N> __device__ __forceinline__ void cp_wait() {
    asm volatile("cp.async.wait_group %0;" :: "n"(N));
}

// ---------------------------------------------------------------------------
// Prep (single launch): round x and 4 weight matrices to fp16.
// ---------------------------------------------------------------------------
#define X4   (MTOT*NC/4)   // 1048576 float4s
#define W4   (NC*NC/4)     // 262144
#define TOT4 (X4 + 4*W4)

__global__ __launch_bounds__(256)
void prep_f16(const float4* __restrict__ x,  const float4* __restrict__ wq,
              const float4* __restrict__ wk, const float4* __restrict__ wv,
              const float4* __restrict__ wp)
{
    const int i = blockIdx.x * 256 + threadIdx.x;
    if (i >= TOT4) return;
    const float4* s; __half* d; int off;
    if (i < X4) { s = x; d = g_x; off = i; }
    else {
        const int j = i - X4;
        const int w = j >> 18;
        off = j & (W4 - 1);
        switch (w) {
            case 0:  s = wq; d = g_wq; break;
            case 1:  s = wk; d = g_wk; break;
            case 2:  s = wv; d = g_wv; break;
            default: s = wp; d = g_wp; break;
        }
    }
    float4 v = s[off];
    __half2 h01 = __floats2half2_rn(v.x, v.y);
    __half2 h23 = __floats2half2_rn(v.z, v.w);
    uint2 u;
    u.x = *(unsigned*)&h01;
    u.y = *(unsigned*)&h23;
    *(uint2*)(d + off * 4) = u;
}

// ---------------------------------------------------------------------------
// FP16 NT GEMM (mma.sync m16n8k16): out[m,n] = sum_k A[m,k]*W[n,k]
// Block 256 (8 warps 4x2), tile 128x64, BK=64 halves, cp.async 2-stage.
// Smem rows: 72 halves (144B = 9x16B, aligned; 8 consecutive rows hit all
// eight 16B lanes -> conflict-free ldmatrix).
// ---------------------------------------------------------------------------
#define GBM 128
#define GBN 64
#define GBK 64
#define GPD 72                            // halves per row
#define A_BYTES (GBM*GPD*2)               // 18432
#define B_BYTES (GBN*GPD*2)               // 9216
#define STG_BYTES (A_BYTES + B_BYTES)     // 27648
#define GEMM_SMEM_BYTES (2*STG_BYTES)     // 55296

__device__ __forceinline__ void gemm_tc(const __half* __restrict__ A,
                                        const __half* __restrict__ W,
                                        float C[2][4][4], int m0, int n0)
{
    extern __shared__ unsigned char smp[];
    const unsigned sbase = smem_u32(smp);

    const int tid  = threadIdx.x;
    const int wid  = tid >> 5;
    const int lane = tid & 31;
    const int wr   = wid >> 1;
    const int wc   = wid & 1;

    // fragment lane offsets (halves)
    const int aRow = lane & 15;
    const int aCol = ((lane >> 4) & 1) << 3;
    const int bRow = (lane & 7) + (((lane >> 4) & 1) << 3);
    const int bCol = ((lane >> 3) & 1) << 3;

    auto stage = [&](unsigned soff, int k0) {
        #pragma unroll
        for (int i = 0; i < 4; i++) {
            const int c   = tid + i * 256;
            const int row = c >> 3;
            const int c8  = (c & 7) << 3;
            cpa16(sbase + soff + (unsigned)(row * GPD + c8) * 2,
                  A + (size_t)(m0 + row) * NC + k0 + c8);
        }
        #pragma unroll
        for (int i = 0; i < 2; i++) {
            const int c   = tid + i * 256;
            const int row = c >> 3;
            const int c8  = (c & 7) << 3;
            cpa16(sbase + soff + A_BYTES + (unsigned)(row * GPD + c8) * 2,
                  W + (size_t)(n0 + row) * NC + k0 + c8);
        }
    };

    stage(0, 0);
    cp_commit();

    const int NIT = NC / GBK;   // 16
    for (int it = 0; it < NIT; it++) {
        cp_wait<0>();
        __syncthreads();
        if (it + 1 < NIT) {
            stage((unsigned)((it + 1) & 1) * STG_BYTES, (it + 1) * GBK);
            cp_commit();
        }
        const unsigned cs = (unsigned)(it & 1) * STG_BYTES;
        const unsigned aBase = sbase + cs;
        const unsigned bBase = sbase + cs + A_BYTES;

        #pragma unroll
        for (int kk = 0; kk < GBK; kk += 16) {
            unsigned a[2][4], b[4][2];
            #pragma unroll
            for (int mt = 0; mt < 2; mt++)
                ldsm4(a[mt][0], a[mt][1], a[mt][2], a[mt][3],
                      aBase + (unsigned)((wr * 32 + mt * 16 + aRow) * GPD + kk + aCol) * 2);
            #pragma unroll
            for (int p = 0; p < 2; p++)
                ldsm4(b[2*p][0], b[2*p][1], b[2*p+1][0], b[2*p+1][1],
                      bBase + (unsigned)((wc * 32 + p * 16 + bRow) * GPD + kk + bCol) * 2);
            #pragma unroll
            for (int mt = 0; mt < 2; mt++)
                #pragma unroll
                for (int nt = 0; nt < 4; nt++)
                    mma_f16(C[mt][nt], a[mt][0], a[mt][1], a[mt][2], a[mt][3],
                            b[nt][0], b[nt][1]);
        }
    }
}

__global__ __launch_bounds__(256, 3)
void qkv_kernel(const float* __restrict__ bq, const float* __restrict__ bk,
                const float* __restrict__ bv)
{
    const __half* W; const float* bias; __half* Out;
    if (blockIdx.z == 0)      { W = g_wq; bias = bq; Out = g_q; }
    else if (blockIdx.z == 1) { W = g_wk; bias = bk; Out = g_k; }
    else                      { W = g_wv; bias = bv; Out = g_v; }

    const int m0 = blockIdx.y * GBM;
    const int n0 = blockIdx.x * GBN;
    float C[2][4][4] = {};
    gemm_tc(g_x, W, C, m0, n0);

    const int lane = threadIdx.x & 31, wid = threadIdx.x >> 5;
    const int g = lane >> 2, t = lane & 3;
    const int wr = wid >> 1, wc = wid & 1;
    const int h = n0 >> 6;

    #pragma unroll
    for (int mt = 0; mt < 2; mt++) {
        #pragma unroll
        for (int rr = 0; rr < 2; rr++) {
            const int m = m0 + wr * 32 + mt * 16 + g + rr * 8;
            const int b = m >> 11;
            const int tt = m & (NT - 1);
            __half* op = Out + (((size_t)(b * NH + h)) * NT + tt) * ND;
            #pragma unroll
            for (int nt = 0; nt < 4; nt++) {
                const int nl = wc * 32 + nt * 8 + 2 * t;
                __half2 hv = __floats2half2_rn(C[mt][nt][rr * 2 + 0] + bias[n0 + nl],
                                               C[mt][nt][rr * 2 + 1] + bias[n0 + nl + 1]);
                *(__half2*)(op + nl) = hv;
            }
        }
    }
}

__global__ __launch_bounds__(256, 3)
void proj_kernel(const float* __restrict__ bp, float* __restrict__ out)
{
    const int m0 = blockIdx.y * GBM;
    const int n0 = blockIdx.x * GBN;
    float C[2][4][4] = {};
    gemm_tc(g_y, g_wp, C, m0, n0);

    const int lane = threadIdx.x & 31, wid = threadIdx.x >> 5;
    const int g = lane >> 2, t = lane & 3;
    const int wr = wid >> 1, wc = wid & 1;

    #pragma unroll
    for (int mt = 0; mt < 2; mt++) {
        #pragma unroll
        for (int rr = 0; rr < 2; rr++) {
            const int m = m0 + wr * 32 + mt * 16 + g + rr * 8;
            #pragma unroll
            for (int nt = 0; nt < 4; nt++) {
                const int n = n0 + wc * 32 + nt * 8 + 2 * t;
                float2 v;
                v.x = C[mt][nt][rr * 2 + 0] + bp[n];
                v.y = C[mt][nt][rr * 2 + 1] + bp[n + 1];
                *(float2*)(out + (size_t)m * NC + n) = v;
            }
        }
    }
}

// ---------------------------------------------------------------------------
// FP16 tensor-core flash attention: 256 thr / 8 warps / 128 q-rows per block.
// K and V tiles both staged [key][d] via pure cp.async (double-buffered);
// V B^T fragments come from ldmatrix.trans — no transpose staging at all.
// ---------------------------------------------------------------------------
#define APDH 72                        // halves per row
#define KVB (64*APDH*2)                // 9216 B per K or V buffer
#define P_BYTES (128*APDH*2)           // 18432
#define ATT_SMEM_BYTES (4*KVB + P_BYTES)   // 55296

__global__ __launch_bounds__(256)
void attn_kernel()
{
    extern __shared__ unsigned char sma[];
    const unsigned sbase = smem_u32(sma);
    const unsigned pBase = sbase + 4 * KVB;
    __half* Psh = (__half*)(sma + 4 * KVB);

    const int tid  = threadIdx.x;
    const int wid  = tid >> 5;
    const int lane = tid & 31;
    const int g    = lane >> 2;
    const int t    = lane & 3;

    const int bh = blockIdx.y;
    const int qb = gridDim.x - 1 - blockIdx.x;   // heavy blocks first
    const int q0 = qb * 128;
    const int rb = wid * 16;

    const int aRow = lane & 15;
    const int aCol = ((lane >> 4) & 1) << 3;               // halves
    const int bRow = (lane & 7) + (((lane >> 4) & 1) << 3);
    const int bCol = ((lane >> 3) & 1) << 3;               // halves
    const int vRow = lane & 15;                            // trans-V: key row
    const int vCol = ((lane >> 4) & 1) << 3;               // trans-V: d chunk

    // ---- Q fragments from gmem halves (x0.125 exact in fp16) ----
    unsigned Qf[4][4];
    {
        const __half* qp = g_q + ((size_t)bh * NT + q0 + rb) * ND;
        const __half2 s2 = __floats2half2_rn(0.125f, 0.125f);
        #pragma unroll
        for (int kt = 0; kt < 4; kt++) {
            __half2 v;
            v = __hmul2(*(const __half2*)(qp + (g)     * ND + kt * 16 + 2 * t), s2);
            Qf[kt][0] = *(unsigned*)&v;
            v = __hmul2(*(const __half2*)(qp + (g + 8) * ND + kt * 16 + 2 * t), s2);
            Qf[kt][1] = *(unsigned*)&v;
            v = __hmul2(*(const __half2*)(qp + (g)     * ND + kt * 16 + 2 * t + 8), s2);
            Qf[kt][2] = *(unsigned*)&v;
            v = __hmul2(*(const __half2*)(qp + (g + 8) * ND + kt * 16 + 2 * t + 8), s2);
            Qf[kt][3] = *(unsigned*)&v;
        }
    }

    float Of[8][4];
    #pragma unroll
    for (int nt = 0; nt < 8; nt++)
        #pragma unroll
        for (int j = 0; j < 4; j++) Of[nt][j] = 0.f;
    float mrow[2] = {-1e30f, -1e30f};
    float lrow[2] = {0.f, 0.f};

    const __half* kbase = g_k + (size_t)bh * NT * ND;
    const __half* vbase = g_v + (size_t)bh * NT * ND;

    const int ntiles = 2 * qb + 2;

    auto stage_tile = [&](int tile, int buf) {
        const unsigned kDst = sbase + (unsigned)buf * KVB;
        const unsigned vDst = sbase + (unsigned)(2 + buf) * KVB;
        #pragma unroll
        for (int i = 0; i < 2; i++) {
            const int c   = tid + i * 256;
            const int row = c >> 3;
            const int c8  = (c & 7) << 3;
            const unsigned o = (unsigned)(row * APDH + c8) * 2;
            cpa16(kDst + o, kbase + (size_t)(tile * 64 + row) * ND + c8);
            cpa16(vDst + o, vbase + (size_t)(tile * 64 + row) * ND + c8);
        }
    };

    stage_tile(0, 0);
    cp_commit();

    for (int kt0 = 0; kt0 < ntiles; kt0++) {
        const int cur = kt0 & 1;
        cp_wait<0>();
        __syncthreads();
        if (kt0 + 1 < ntiles) {
            stage_tile(kt0 + 1, cur ^ 1);
            cp_commit();
        }
        const unsigned kBuf = sbase + (unsigned)cur * KVB;
        const unsigned vBuf = sbase + (unsigned)(2 + cur) * KVB;

        const bool active = (kt0 * 64) <= (q0 + rb + 15);
        if (active) {
            // ---- S = Q K^T  (k16 over d, 4 steps) ----
            float Sf[8][4];
            #pragma unroll
            for (int nt = 0; nt < 8; nt++)
                #pragma unroll
                for (int j = 0; j < 4; j++) Sf[nt][j] = 0.f;

            #pragma unroll
            for (int kt = 0; kt < 4; kt++) {
                unsigned b[8][2];
                #pragma unroll
                for (int p = 0; p < 4; p++)
                    ldsm4(b[2*p][0], b[2*p][1], b[2*p+1][0], b[2*p+1][1],
                          kBuf + (unsigned)((p * 16 + bRow) * APDH + kt * 16 + bCol) * 2);
                #pragma unroll
                for (int nt = 0; nt < 8; nt++)
                    mma_f16(Sf[nt], Qf[kt][0], Qf[kt][1], Qf[kt][2], Qf[kt][3],
                            b[nt][0], b[nt][1]);
            }

            // ---- causal mask (diagonal tiles only) ----
            if (kt0 >= 2 * qb) {
                #pragma unroll
                for (int nt = 0; nt < 8; nt++)
                    #pragma unroll
                    for (int j = 0; j < 4; j++) {
                        const int key = kt0 * 64 + nt * 8 + 2 * t + (j & 1);
                        const int qr  = q0 + rb + g + (j >> 1) * 8;
                        if (key > qr) Sf[nt][j] = -1e30f;
                    }
            }

            // ---- online softmax ----
            #pragma unroll
            for (int r = 0; r < 2; r++) {
                float rm = -1e30f;
                #pragma unroll
                for (int nt = 0; nt < 8; nt++) {
                    rm = fmaxf(rm, Sf[nt][2 * r]);
                    rm = fmaxf(rm, Sf[nt][2 * r + 1]);
                }
                rm = fmaxf(rm, __shfl_xor_sync(0xffffffff, rm, 1));
                rm = fmaxf(rm, __shfl_xor_sync(0xffffffff, rm, 2));
                const float mn   = fmaxf(mrow[r], rm);
                const float corr = __expf(mrow[r] - mn);
                mrow[r] = mn;
                float rs = 0.f;
                #pragma unroll
                for (int nt = 0; nt < 8; nt++) {
                    const float p0 = __expf(Sf[nt][2 * r]     - mn);
                    const float p1 = __expf(Sf[nt][2 * r + 1] - mn);
                    Sf[nt][2 * r] = p0; Sf[nt][2 * r + 1] = p1;
                    rs += p0 + p1;
                }
                rs += __shfl_xor_sync(0xffffffff, rs, 1);
                rs += __shfl_xor_sync(0xffffffff, rs, 2);
                lrow[r] = lrow[r] * corr + rs;
                #pragma unroll
                for (int nt = 0; nt < 8; nt++) {
                    Of[nt][2 * r]     *= corr;
                    Of[nt][2 * r + 1] *= corr;
                }
            }

            // ---- write P (half2 pairs) into this warp's slice ----
            #pragma unroll
            for (int nt = 0; nt < 8; nt++) {
                __half2 h0 = __floats2half2_rn(Sf[nt][0], Sf[nt][1]);
                *(__half2*)(Psh + (rb + g)     * APDH + nt * 8 + 2 * t) = h0;
                __half2 h1 = __floats2half2_rn(Sf[nt][2], Sf[nt][3]);
                *(__half2*)(Psh + (rb + g + 8) * APDH + nt * 8 + 2 * t) = h1;
            }
            __syncwarp();

            // ---- O += P V  (k16 over keys, 4 steps; V via ldmatrix.trans) ----
            #pragma unroll
            for (int kt = 0; kt < 4; kt++) {
                unsigned a0, a1, a2, a3;
                ldsm4(a0, a1, a2, a3,
                      pBase + (unsigned)((rb + aRow) * APDH + kt * 16 + aCol) * 2);
                unsigned b[8][2];
                #pragma unroll
                for (int p = 0; p < 4; p++)
                    ldsm4t(b[2*p][0], b[2*p][1], b[2*p+1][0], b[2*p+1][1],
                           vBuf + (unsigned)((kt * 16 + vRow) * APDH + p * 16 + vCol) * 2);
                #pragma unroll
                for (int nt = 0; nt < 8; nt++)
                    mma_f16(Of[nt], a0, a1, a2, a3, b[nt][0], b[nt][1]);
            }
        }
        __syncthreads();
    }

    // ---- epilogue: divide by l, store half for proj ----
    const float inv0 = 1.0f / lrow[0];
    const float inv1 = 1.0f / lrow[1];
    const int b = bh >> 4;
    const int h = bh & 15;
    __half* yp = g_y + ((size_t)(b * NT) + q0 + rb) * NC + h * ND;

    #pragma unroll
    for (int nt = 0; nt < 8; nt++) {
        const int c = nt * 8 + 2 * t;
        __half2 v0 = __floats2half2_rn(Of[nt][0] * inv0, Of[nt][1] * inv0);
        *(__half2*)(yp + (size_t)g * NC + c) = v0;
        __half2 v1 = __floats2half2_rn(Of[nt][2] * inv1, Of[nt][3] * inv1);
        *(__half2*)(yp + (size_t)(g + 8) * NC + c) = v1;
    }
}

// ---------------------------------------------------------------------------
extern "C" void kernel_launch(void* const* d_in, const int* in_sizes, int n_in,
                              void* d_out, int out_size)
{
    const float* x  = (const float*)d_in[0];
    const float* Wk = (const float*)d_in[1];
    const float* bk = (const float*)d_in[2];
    const float* Wq = (const float*)d_in[3];
    const float* bq = (const float*)d_in[4];
    const float* Wv = (const float*)d_in[5];
    const float* bv = (const float*)d_in[6];
    const float* Wp = (const float*)d_in[7];
    const float* bp = (const float*)d_in[8];
    float* out = (float*)d_out;

    static bool attr_done = false;
    if (!attr_done) {
        cudaFuncSetAttribute(qkv_kernel,
                             cudaFuncAttributeMaxDynamicSharedMemorySize, GEMM_SMEM_BYTES);
        cudaFuncSetAttribute(proj_kernel,
                             cudaFuncAttributeMaxDynamicSharedMemorySize, GEMM_SMEM_BYTES);
        cudaFuncSetAttribute(attn_kernel,
                             cudaFuncAttributeMaxDynamicSharedMemorySize, ATT_SMEM_BYTES);
        attr_done = true;
    }

    prep_f16<<<(TOT4 + 255) / 256, 256>>>((const float4*)x,  (const float4*)Wq,
                                          (const float4*)Wk, (const float4*)Wv,
                                          (const float4*)Wp);

    dim3 gq(NC / GBN, MTOT / GBM, 3);
    qkv_kernel<<<gq, 256, GEMM_SMEM_BYTES>>>(bq, bk, bv);

    dim3 ga(NT / 128, NB * NH);
    attn_kernel<<<ga, 256, ATT_SMEM_BYTES>>>();

    dim3 gp(NC / GBN, MTOT / GBM);
    proj_kernel<<<gp, 256, GEMM_SMEM_BYTES>>>(bp, out);
}

// round 12
// speedup vs baseline: 2.6193x; 1.0946x over previous
#include <cuda_runtime.h>
#include <cuda_fp16.h>
#include <math.h>
#include <stdint.h>

#define NB 2
#define NT 2048
#define NC 1024
#define NH 16
#define ND 64
#define MTOT (NB*NT)   // 4096

// Scratch (device globals) — fp16
__device__ __half g_q[NB*NH*NT*ND];
__device__ __half g_k[NB*NH*NT*ND];
__device__ __half g_v[NB*NH*NT*ND];
__device__ __half g_y[NB*NT*NC];
__device__ __half g_x[MTOT*NC];
__device__ __half g_wq[NC*NC];
__device__ __half g_wk[NC*NC];
__device__ __half g_wv[NC*NC];
__device__ __half g_wp[NC*NC];

__device__ __forceinline__ unsigned smem_u32(const void* p) {
    unsigned r;
    asm("{ .reg .u64 t; cvta.to.shared.u64 t, %1; cvt.u32.u64 %0, t; }"
        : "=r"(r) : "l"(p));
    return r;
}

__device__ __forceinline__ void ldsm4(unsigned& r0, unsigned& r1,
                                      unsigned& r2, unsigned& r3, unsigned addr)
{
    asm volatile("ldmatrix.sync.aligned.m8n8.x4.shared.b16 {%0,%1,%2,%3}, [%4];"
                 : "=r"(r0), "=r"(r1), "=r"(r2), "=r"(r3) : "r"(addr));
}
__device__ __forceinline__ void ldsm4t(unsigned& r0, unsigned& r1,
                                       unsigned& r2, unsigned& r3, unsigned addr)
{
    asm volatile("ldmatrix.sync.aligned.m8n8.x4.trans.shared.b16 {%0,%1,%2,%3}, [%4];"
                 : "=r"(r0), "=r"(r1), "=r"(r2), "=r"(r3) : "r"(addr));
}

// fp16 MMA, fp32 accumulate: D(16x8) += A(16x16) * B(16x8)
__device__ __forceinline__ void mma_f16(float c[4], unsigned a0, unsigned a1,
                                        unsigned a2, unsigned a3,
                                        unsigned b0, unsigned b1)
{
    asm volatile(
        "mma.sync.aligned.m16n8k16.row.col.f32.f16.f16.f32 "
        "{%0,%1,%2,%3}, {%4,%5,%6,%7}, {%8,%9}, {%0,%1,%2,%3};"
        : "+f"(c[0]), "+f"(c[1]), "+f"(c[2]), "+f"(c[3])
        : "r"(a0), "r"(a1), "r"(a2), "r"(a3), "r"(b0), "r"(b1));
}

__device__ __forceinline__ void cpa16(unsigned dst, const void* src) {
    asm volatile("cp.async.cg.shared.global [%0], [%1], 16;" :: "r"(dst), "l"(src));
}
__device__ __forceinline__ void cp_commit() {
    asm volatile("cp.async.commit_group;");
}
template<int N> __device__ __forceinline__ void cp_wait() {
    asm volatile("cp.async.wait_group %0;" :: "n"(N));
}

// ---------------------------------------------------------------------------
// Prep (single launch): round x and 4 weight matrices to fp16.
// ---------------------------------------------------------------------------
#define X4   (MTOT*NC/4)
#define W4   (NC*NC/4)
#define TOT4 (X4 + 4*W4)

__global__ __launch_bounds__(256)
void prep_f16(const float4* __restrict__ x,  const float4* __restrict__ wq,
              const float4* __restrict__ wk, const float4* __restrict__ wv,
              const float4* __restrict__ wp)
{
    const int i = blockIdx.x * 256 + threadIdx.x;
    if (i >= TOT4) return;
    const float4* s; __half* d; int off;
    if (i < X4) { s = x; d = g_x; off = i; }
    else {
        const int j = i - X4;
        const int w = j >> 18;
        off = j & (W4 - 1);
        switch (w) {
            case 0:  s = wq; d = g_wq; break;
            case 1:  s = wk; d = g_wk; break;
            case 2:  s = wv; d = g_wv; break;
            default: s = wp; d = g_wp; break;
        }
    }
    float4 v = s[off];
    __half2 h01 = __floats2half2_rn(v.x, v.y);
    __half2 h23 = __floats2half2_rn(v.z, v.w);
    uint2 u;
    u.x = *(unsigned*)&h01;
    u.y = *(unsigned*)&h23;
    *(uint2*)(d + off * 4) = u;
}

// ---------------------------------------------------------------------------
// FP16 NT GEMM: block tile 128x128, warp tile 32x64 (8 warps, 4x2), BK=64,
// cp.async 2-stage. Per k16 step/warp: 6 LDSM -> 16 MMA.
// ---------------------------------------------------------------------------
#define GBM 128
#define GBN 128
#define GBK 64
#define GPD 72                            // halves per row (144B pitch)
#define A_BYTES (GBM*GPD*2)               // 18432
#define B_BYTES (GBN*GPD*2)               // 18432
#define STG_BYTES (A_BYTES + B_BYTES)     // 36864
#define GEMM_SMEM_BYTES (2*STG_BYTES)     // 73728

__device__ __forceinline__ void gemm_tc(const __half* __restrict__ A,
                                        const __half* __restrict__ W,
                                        float C[2][8][4], int m0, int n0)
{
    extern __shared__ unsigned char smp[];
    const unsigned sbase = smem_u32(smp);

    const int tid  = threadIdx.x;
    const int wid  = tid >> 5;
    const int lane = tid & 31;
    const int wr   = wid >> 1;   // m offset wr*32
    const int wc   = wid & 1;    // n offset wc*64

    const int aRow = lane & 15;
    const int aCol = ((lane >> 4) & 1) << 3;
    const int bRow = (lane & 7) + (((lane >> 4) & 1) << 3);
    const int bCol = ((lane >> 3) & 1) << 3;

    // staging: A and B each 128 rows x 8 chunks = 1024 chunks; 4 per thread
    auto stage = [&](unsigned soff, int k0) {
        #pragma unroll
        for (int i = 0; i < 4; i++) {
            const int c   = tid + i * 256;
            const int row = c >> 3;
            const int c8  = (c & 7) << 3;
            cpa16(sbase + soff + (unsigned)(row * GPD + c8) * 2,
                  A + (size_t)(m0 + row) * NC + k0 + c8);
        }
        #pragma unroll
        for (int i = 0; i < 4; i++) {
            const int c   = tid + i * 256;
            const int row = c >> 3;
            const int c8  = (c & 7) << 3;
            cpa16(sbase + soff + A_BYTES + (unsigned)(row * GPD + c8) * 2,
                  W + (size_t)(n0 + row) * NC + k0 + c8);
        }
    };

    stage(0, 0);
    cp_commit();

    const int NIT = NC / GBK;   // 16
    for (int it = 0; it < NIT; it++) {
        cp_wait<0>();
        __syncthreads();
        if (it + 1 < NIT) {
            stage((unsigned)((it + 1) & 1) * STG_BYTES, (it + 1) * GBK);
            cp_commit();
        }
        const unsigned cs = (unsigned)(it & 1) * STG_BYTES;
        const unsigned aBase = sbase + cs;
        const unsigned bBase = sbase + cs + A_BYTES;

        #pragma unroll
        for (int kk = 0; kk < GBK; kk += 16) {
            unsigned a[2][4], b[8][2];
            #pragma unroll
            for (int mt = 0; mt < 2; mt++)
                ldsm4(a[mt][0], a[mt][1], a[mt][2], a[mt][3],
                      aBase + (unsigned)((wr * 32 + mt * 16 + aRow) * GPD + kk + aCol) * 2);
            #pragma unroll
            for (int p = 0; p < 4; p++)
                ldsm4(b[2*p][0], b[2*p][1], b[2*p+1][0], b[2*p+1][1],
                      bBase + (unsigned)((wc * 64 + p * 16 + bRow) * GPD + kk + bCol) * 2);
            #pragma unroll
            for (int mt = 0; mt < 2; mt++)
                #pragma unroll
                for (int nt = 0; nt < 8; nt++)
                    mma_f16(C[mt][nt], a[mt][0], a[mt][1], a[mt][2], a[mt][3],
                            b[nt][0], b[nt][1]);
        }
    }
}

__global__ __launch_bounds__(256, 2)
void qkv_kernel(const float* __restrict__ bq, const float* __restrict__ bk,
                const float* __restrict__ bv)
{
    const __half* W; const float* bias; __half* Out;
    if (blockIdx.z == 0)      { W = g_wq; bias = bq; Out = g_q; }
    else if (blockIdx.z == 1) { W = g_wk; bias = bk; Out = g_k; }
    else                      { W = g_wv; bias = bv; Out = g_v; }

    const int m0 = blockIdx.y * GBM;
    const int n0 = blockIdx.x * GBN;
    float C[2][8][4] = {};
    gemm_tc(g_x, W, C, m0, n0);

    const int lane = threadIdx.x & 31, wid = threadIdx.x >> 5;
    const int g = lane >> 2, t = lane & 3;
    const int wr = wid >> 1, wc = wid & 1;

    #pragma unroll
    for (int mt = 0; mt < 2; mt++) {
        #pragma unroll
        for (int rr = 0; rr < 2; rr++) {
            const int m = m0 + wr * 32 + mt * 16 + g + rr * 8;
            const int b = m >> 11;
            const int tt = m & (NT - 1);
            #pragma unroll
            for (int nt = 0; nt < 8; nt++) {
                const int n  = n0 + wc * 64 + nt * 8 + 2 * t;
                const int h  = n >> 6;
                const int hd = n & 63;
                __half* op = Out + (((size_t)(b * NH + h)) * NT + tt) * ND + hd;
                __half2 hv = __floats2half2_rn(C[mt][nt][rr * 2 + 0] + bias[n],
                                               C[mt][nt][rr * 2 + 1] + bias[n + 1]);
                *(__half2*)op = hv;
            }
        }
    }
}

__global__ __launch_bounds__(256, 2)
void proj_kernel(const float* __restrict__ bp, float* __restrict__ out)
{
    const int m0 = blockIdx.y * GBM;
    const int n0 = blockIdx.x * GBN;
    float C[2][8][4] = {};
    gemm_tc(g_y, g_wp, C, m0, n0);

    const int lane = threadIdx.x & 31, wid = threadIdx.x >> 5;
    const int g = lane >> 2, t = lane & 3;
    const int wr = wid >> 1, wc = wid & 1;

    #pragma unroll
    for (int mt = 0; mt < 2; mt++) {
        #pragma unroll
        for (int rr = 0; rr < 2; rr++) {
            const int m = m0 + wr * 32 + mt * 16 + g + rr * 8;
            #pragma unroll
            for (int nt = 0; nt < 8; nt++) {
                const int n = n0 + wc * 64 + nt * 8 + 2 * t;
                float2 v;
                v.x = C[mt][nt][rr * 2 + 0] + bp[n];
                v.y = C[mt][nt][rr * 2 + 1] + bp[n + 1];
                *(float2*)(out + (size_t)m * NC + n) = v;
            }
        }
    }
}

// ---------------------------------------------------------------------------
// FP16 flash attention, REGISTER-P: S fragments repack directly into the
// A-fragments of the P*V mma (no smem P buffer at all).
// 256 thr / 8 warps / 128 q-rows per block; K,V staged [key][d] via cp.async.
// ---------------------------------------------------------------------------
#define APDH 72
#define KVB (64*APDH*2)                 // 9216 B per buffer
#define ATT_SMEM_BYTES (4*KVB)          // K0 K1 V0 V1 = 36864

__global__ __launch_bounds__(256)
void attn_kernel()
{
    extern __shared__ unsigned char sma[];
    const unsigned sbase = smem_u32(sma);

    const int tid  = threadIdx.x;
    const int wid  = tid >> 5;
    const int lane = tid & 31;
    const int g    = lane >> 2;
    const int t    = lane & 3;

    const int bh = blockIdx.y;
    const int qb = gridDim.x - 1 - blockIdx.x;   // heavy blocks first
    const int q0 = qb * 128;
    const int rb = wid * 16;

    const int bRow = (lane & 7) + (((lane >> 4) & 1) << 3);
    const int bCol = ((lane >> 3) & 1) << 3;
    const int vRow = lane & 15;
    const int vCol = ((lane >> 4) & 1) << 3;

    // ---- Q fragments from gmem (x0.125 exact in fp16) ----
    unsigned Qf[4][4];
    {
        const __half* qp = g_q + ((size_t)bh * NT + q0 + rb) * ND;
        const __half2 s2 = __floats2half2_rn(0.125f, 0.125f);
        #pragma unroll
        for (int kt = 0; kt < 4; kt++) {
            __half2 v;
            v = __hmul2(*(const __half2*)(qp + (g)     * ND + kt * 16 + 2 * t), s2);
            Qf[kt][0] = *(unsigned*)&v;
            v = __hmul2(*(const __half2*)(qp + (g + 8) * ND + kt * 16 + 2 * t), s2);
            Qf[kt][1] = *(unsigned*)&v;
            v = __hmul2(*(const __half2*)(qp + (g)     * ND + kt * 16 + 2 * t + 8), s2);
            Qf[kt][2] = *(unsigned*)&v;
            v = __hmul2(*(const __half2*)(qp + (g + 8) * ND + kt * 16 + 2 * t + 8), s2);
            Qf[kt][3] = *(unsigned*)&v;
        }
    }

    float Of[8][4];
    #pragma unroll
    for (int nt = 0; nt < 8; nt++)
        #pragma unroll
        for (int j = 0; j < 4; j++) Of[nt][j] = 0.f;
    float mrow[2] = {-1e30f, -1e30f};
    float lrow[2] = {0.f, 0.f};

    const __half* kbase = g_k + (size_t)bh * NT * ND;
    const __half* vbase = g_v + (size_t)bh * NT * ND;

    const int ntiles = 2 * qb + 2;

    auto stage_tile = [&](int tile, int buf) {
        const unsigned kDst = sbase + (unsigned)buf * KVB;
        const unsigned vDst = sbase + (unsigned)(2 + buf) * KVB;
        #pragma unroll
        for (int i = 0; i < 2; i++) {
            const int c   = tid + i * 256;
            const int row = c >> 3;
            const int c8  = (c & 7) << 3;
            const unsigned o = (unsigned)(row * APDH + c8) * 2;
            cpa16(kDst + o, kbase + (size_t)(tile * 64 + row) * ND + c8);
            cpa16(vDst + o, vbase + (size_t)(tile * 64 + row) * ND + c8);
        }
    };

    stage_tile(0, 0);
    cp_commit();

    for (int kt0 = 0; kt0 < ntiles; kt0++) {
        const int cur = kt0 & 1;
        cp_wait<0>();
        __syncthreads();
        if (kt0 + 1 < ntiles) {
            stage_tile(kt0 + 1, cur ^ 1);
            cp_commit();
        }
        const unsigned kBuf = sbase + (unsigned)cur * KVB;
        const unsigned vBuf = sbase + (unsigned)(2 + cur) * KVB;

        const bool active = (kt0 * 64) <= (q0 + rb + 15);
        if (active) {
            // ---- S = Q K^T ----
            float Sf[8][4];
            #pragma unroll
            for (int nt = 0; nt < 8; nt++)
                #pragma unroll
                for (int j = 0; j < 4; j++) Sf[nt][j] = 0.f;

            #pragma unroll
            for (int kt = 0; kt < 4; kt++) {
                unsigned b[8][2];
                #pragma unroll
                for (int p = 0; p < 4; p++)
                    ldsm4(b[2*p][0], b[2*p][1], b[2*p+1][0], b[2*p+1][1],
                          kBuf + (unsigned)((p * 16 + bRow) * APDH + kt * 16 + bCol) * 2);
                #pragma unroll
                for (int nt = 0; nt < 8; nt++)
                    mma_f16(Sf[nt], Qf[kt][0], Qf[kt][1], Qf[kt][2], Qf[kt][3],
                            b[nt][0], b[nt][1]);
            }

            // ---- causal mask (diagonal tiles only) ----
            if (kt0 >= 2 * qb) {
                #pragma unroll
                for (int nt = 0; nt < 8; nt++)
                    #pragma unroll
                    for (int j = 0; j < 4; j++) {
                        const int key = kt0 * 64 + nt * 8 + 2 * t + (j & 1);
                        const int qr  = q0 + rb + g + (j >> 1) * 8;
                        if (key > qr) Sf[nt][j] = -1e30f;
                    }
            }

            // ---- online softmax ----
            #pragma unroll
            for (int r = 0; r < 2; r++) {
                float rm = -1e30f;
                #pragma unroll
                for (int nt = 0; nt < 8; nt++) {
                    rm = fmaxf(rm, Sf[nt][2 * r]);
                    rm = fmaxf(rm, Sf[nt][2 * r + 1]);
                }
                rm = fmaxf(rm, __shfl_xor_sync(0xffffffff, rm, 1));
                rm = fmaxf(rm, __shfl_xor_sync(0xffffffff, rm, 2));
                const float mn   = fmaxf(mrow[r], rm);
                const float corr = __expf(mrow[r] - mn);
                mrow[r] = mn;
                float rs = 0.f;
                #pragma unroll
                for (int nt = 0; nt < 8; nt++) {
                    const float p0 = __expf(Sf[nt][2 * r]     - mn);
                    const float p1 = __expf(Sf[nt][2 * r + 1] - mn);
                    Sf[nt][2 * r] = p0; Sf[nt][2 * r + 1] = p1;
                    rs += p0 + p1;
                }
                rs += __shfl_xor_sync(0xffffffff, rs, 1);
                rs += __shfl_xor_sync(0xffffffff, rs, 2);
                lrow[r] = lrow[r] * corr + rs;
                #pragma unroll
                for (int nt = 0; nt < 8; nt++) {
                    Of[nt][2 * r]     *= corr;
                    Of[nt][2 * r + 1] *= corr;
                }
            }

            // ---- O += P V : P packed straight from S fragments ----
            #pragma unroll
            for (int kt = 0; kt < 4; kt++) {
                __half2 p0 = __floats2half2_rn(Sf[2*kt][0],   Sf[2*kt][1]);
                __half2 p1 = __floats2half2_rn(Sf[2*kt][2],   Sf[2*kt][3]);
                __half2 p2 = __floats2half2_rn(Sf[2*kt+1][0], Sf[2*kt+1][1]);
                __half2 p3 = __floats2half2_rn(Sf[2*kt+1][2], Sf[2*kt+1][3]);
                const unsigned a0 = *(unsigned*)&p0;
                const unsigned a1 = *(unsigned*)&p1;
                const unsigned a2 = *(unsigned*)&p2;
                const unsigned a3 = *(unsigned*)&p3;
                unsigned b[8][2];
                #pragma unroll
                for (int p = 0; p < 4; p++)
                    ldsm4t(b[2*p][0], b[2*p][1], b[2*p+1][0], b[2*p+1][1],
                           vBuf + (unsigned)((kt * 16 + vRow) * APDH + p * 16 + vCol) * 2);
                #pragma unroll
                for (int nt = 0; nt < 8; nt++)
                    mma_f16(Of[nt], a0, a1, a2, a3, b[nt][0], b[nt][1]);
            }
        }
        __syncthreads();
    }

    // ---- epilogue: divide by l, store half for proj ----
    const float inv0 = 1.0f / lrow[0];
    const float inv1 = 1.0f / lrow[1];
    const int b = bh >> 4;
    const int h = bh & 15;
    __half* yp = g_y + ((size_t)(b * NT) + q0 + rb) * NC + h * ND;

    #pragma unroll
    for (int nt = 0; nt < 8; nt++) {
        const int c = nt * 8 + 2 * t;
        __half2 v0 = __floats2half2_rn(Of[nt][0] * inv0, Of[nt][1] * inv0);
        *(__half2*)(yp + (size_t)g * NC + c) = v0;
        __half2 v1 = __floats2half2_rn(Of[nt][2] * inv1, Of[nt][3] * inv1);
        *(__half2*)(yp + (size_t)(g + 8) * NC + c) = v1;
    }
}

// ---------------------------------------------------------------------------
extern "C" void kernel_launch(void* const* d_in, const int* in_sizes, int n_in,
                              void* d_out, int out_size)
{
    const float* x  = (const float*)d_in[0];
    const float* Wk = (const float*)d_in[1];
    const float* bk = (const float*)d_in[2];
    const float* Wq = (const float*)d_in[3];
    const float* bq = (const float*)d_in[4];
    const float* Wv = (const float*)d_in[5];
    const float* bv = (const float*)d_in[6];
    const float* Wp = (const float*)d_in[7];
    const float* bp = (const float*)d_in[8];
    float* out = (float*)d_out;

    static bool attr_done = false;
    if (!attr_done) {
        cudaFuncSetAttribute(qkv_kernel,
                             cudaFuncAttributeMaxDynamicSharedMemorySize, GEMM_SMEM_BYTES);
        cudaFuncSetAttribute(proj_kernel,
                             cudaFuncAttributeMaxDynamicSharedMemorySize, GEMM_SMEM_BYTES);
        cudaFuncSetAttribute(attn_kernel,
                             cudaFuncAttributeMaxDynamicSharedMemorySize, ATT_SMEM_BYTES);
        attr_done = true;
    }

    prep_f16<<<(TOT4 + 255) / 256, 256>>>((const float4*)x,  (const float4*)Wq,
                                          (const float4*)Wk, (const float4*)Wv,
                                          (const float4*)Wp);

    dim3 gq(NC / GBN, MTOT / GBM, 3);
    qkv_kernel<<<gq, 256, GEMM_SMEM_BYTES>>>(bq, bk, bv);

    dim3 ga(NT / 128, NB * NH);
    attn_kernel<<<ga, 256, ATT_SMEM_BYTES>>>();

    dim3 gp(NC / GBN, MTOT / GBM);
    proj_kernel<<<gp, 256, GEMM_SMEM_BYTES>>>(bp, out);
}